// round 4
// baseline (speedup 1.0000x reference)
#include <cuda_runtime.h>

#define THREADS 256

// One warp computes ONE score (pos OR neg) for one triple.
// pos-warp w<n: triple w, loads v,h,r,t.  neg-warp w>=n: triple w-n, loads v,nh,nr,nt.
// Projection linearity: sum|P(h)+P(r)-P(t)| = sum|P(h+r-t)| with shared v.
__global__ __launch_bounds__(THREADS, 8)
void transh_score_split_kernel(
    const int* __restrict__ pos_h, const int* __restrict__ pos_t, const int* __restrict__ pos_r,
    const int* __restrict__ neg_h, const int* __restrict__ neg_t, const int* __restrict__ neg_r,
    const float4* __restrict__ ent,    // [ENT, 32] float4
    const float4* __restrict__ vvrel,  // [ENT, 32] float4
    const float4* __restrict__ bases,  // [REL, 32] float4
    float* __restrict__ out, int n)
{
    const int warp = (blockIdx.x * blockDim.x + threadIdx.x) >> 5;
    const int lane = threadIdx.x & 31;
    if (warp >= 2 * n) return;

    const bool is_pos = (warp < n);
    const int  i      = is_pos ? warp : warp - n;

    // Index loads (neg warps also need pos_r for the projection vector).
    const int ir = __ldg(pos_r + i);
    const int ih = is_pos ? __ldg(pos_h + i) : __ldg(neg_h + i);
    const int it = is_pos ? __ldg(pos_t + i) : __ldg(neg_t + i);
    const int iv = is_pos ? ir              : __ldg(neg_r + i);

    // Row gathers: 128 floats = 32 float4, one per lane.
    const float4 v = __ldg(bases + (size_t)ir * 32 + lane);
    const float4 h = __ldg(ent   + (size_t)ih * 32 + lane);
    const float4 t = __ldg(ent   + (size_t)it * 32 + lane);
    const float4 r = __ldg(vvrel + (size_t)iv * 32 + lane);

    float4 d;
    d.x = h.x + r.x - t.x;  d.y = h.y + r.y - t.y;
    d.z = h.z + r.z - t.z;  d.w = h.w + r.w - t.w;

    float pvv = v.x * v.x + v.y * v.y + v.z * v.z + v.w * v.w;
    float pvd = v.x * d.x + v.y * d.y + v.z * d.z + v.w * d.w;
    #pragma unroll
    for (int o = 16; o > 0; o >>= 1) {
        pvv += __shfl_xor_sync(0xFFFFFFFFu, pvv, o);
        pvd += __shfl_xor_sync(0xFFFFFFFFu, pvd, o);
    }
    const float c = pvd / pvv;

    float s = fabsf(d.x - c * v.x) + fabsf(d.y - c * v.y)
            + fabsf(d.z - c * v.z) + fabsf(d.w - c * v.w);
    #pragma unroll
    for (int o = 16; o > 0; o >>= 1)
        s += __shfl_xor_sync(0xFFFFFFFFu, s, o);

    if (lane == 0)
        out[warp] = s;   // pos warps write out[0:n], neg warps out[n:2n]
}

extern "C" void kernel_launch(void* const* d_in, const int* in_sizes, int n_in,
                              void* d_out, int out_size)
{
    const int*    pos_h = (const int*)d_in[0];
    const int*    pos_t = (const int*)d_in[1];
    const int*    pos_r = (const int*)d_in[2];
    const int*    neg_h = (const int*)d_in[3];
    const int*    neg_t = (const int*)d_in[4];
    const int*    neg_r = (const int*)d_in[5];
    const float4* ent   = (const float4*)d_in[6];
    const float4* vvrel = (const float4*)d_in[7];
    const float4* bases = (const float4*)d_in[8];
    float* out = (float*)d_out;

    const int n = in_sizes[0];  // 65536 triples
    const int total_warps = 2 * n;
    const int warps_per_block = THREADS / 32;
    const int blocks = (total_warps + warps_per_block - 1) / warps_per_block;
    transh_score_split_kernel<<<blocks, THREADS>>>(
        pos_h, pos_t, pos_r, neg_h, neg_t, neg_r, ent, vvrel, bases, out, n);
}